// round 6
// baseline (speedup 1.0000x reference)
#include <cuda_runtime.h>
#include <cuda_bf16.h>
#include <cstdint>
#include <math.h>

// Problem constants (B=4, S=1024, H=2048, I=2048, E=8, top_k=2)
#define TT   4096
#define HH   2048
#define EE   8
#define II   2048
#define I2   4096
#define NASS (TT * 2)
#define KDIM 2048
#define BM   128
#define BN   128
#define BK   32
#define NCHUNK (KDIM / BK)   // 64
#define STRD 40              // halves per smem row (80B; row step=20 banks -> conflict-free ldmatrix)
#define TILEB (BM * STRD * 2)          // 10240 B per tile
#define STG   (4 * TILEB)              // 40960 B per stage (Ah, Al, Bh, Bl)
#define NSTAGE 4
#define SMEM_DYN (NSTAGE * STG)        // 163840 B

// ---------------- scratch (device globals) ----------------
__device__ int   g_topk_idx[TT * 2];
__device__ float g_topk_w[TT * 2];
__device__ int   g_cnt[EE];
__device__ int   g_off[EE];
__device__ int   g_cur[EE];
__device__ int   g_rowtok[NASS];
__device__ float g_roww[NASS];
// pre-split bf16 operands
__device__ __nv_bfloat16 g_xhi[(size_t)TT * HH],  g_xlo[(size_t)TT * HH];    // 16MB x2
__device__ __nv_bfloat16 g_w1hi[(size_t)EE * I2 * HH], g_w1lo[(size_t)EE * I2 * HH];   // 128MB x2
__device__ __nv_bfloat16 g_w2hi[(size_t)EE * HH * II], g_w2lo[(size_t)EE * HH * II];   // 64MB x2
__device__ __nv_bfloat16 g_acthi[(size_t)NASS * II], g_actlo[(size_t)NASS * II];       // 32MB x2

// ---------------- helpers ----------------
__device__ __forceinline__ uint32_t s2u(const void* p) {
    uint32_t a;
    asm("{ .reg .u64 t; cvta.to.shared.u64 t, %1; cvt.u32.u64 %0, t; }" : "=r"(a) : "l"(p));
    return a;
}
__device__ __forceinline__ void cpasync16(uint32_t dst, const void* src) {
    asm volatile("cp.async.cg.shared.global [%0], [%1], 16;" :: "r"(dst), "l"(src));
}
__device__ __forceinline__ void cp_commit() { asm volatile("cp.async.commit_group;"); }
template <int N>
__device__ __forceinline__ void cp_wait() { asm volatile("cp.async.wait_group %0;" :: "n"(N)); }

__device__ __forceinline__ void ldm_x4(uint32_t* r, uint32_t addr) {
    asm volatile("ldmatrix.sync.aligned.m8n8.x4.shared.b16 {%0,%1,%2,%3}, [%4];"
                 : "=r"(r[0]), "=r"(r[1]), "=r"(r[2]), "=r"(r[3]) : "r"(addr));
}
__device__ __forceinline__ void mma16816(float* d, const uint32_t* a, uint32_t b0, uint32_t b1) {
    asm volatile("mma.sync.aligned.m16n8k16.row.col.f32.bf16.bf16.f32 "
                 "{%0,%1,%2,%3}, {%4,%5,%6,%7}, {%8,%9}, {%0,%1,%2,%3};"
                 : "+f"(d[0]), "+f"(d[1]), "+f"(d[2]), "+f"(d[3])
                 : "r"(a[0]), "r"(a[1]), "r"(a[2]), "r"(a[3]), "r"(b0), "r"(b1));
}

// ---------------- split-convert kernels ----------------
__global__ void convert_split(const float4* __restrict__ src,
                              __nv_bfloat162* __restrict__ hi2,
                              __nv_bfloat162* __restrict__ lo2, size_t n4) {
    size_t stride = (size_t)gridDim.x * blockDim.x;
    for (size_t i = (size_t)blockIdx.x * blockDim.x + threadIdx.x; i < n4; i += stride) {
        float4 v = src[i];
        __nv_bfloat16 h0 = __float2bfloat16_rn(v.x), h1 = __float2bfloat16_rn(v.y);
        __nv_bfloat16 h2 = __float2bfloat16_rn(v.z), h3 = __float2bfloat16_rn(v.w);
        hi2[i * 2 + 0] = __halves2bfloat162(h0, h1);
        hi2[i * 2 + 1] = __halves2bfloat162(h2, h3);
        lo2[i * 2 + 0] = __floats2bfloat162_rn(v.x - __bfloat162float(h0),
                                               v.y - __bfloat162float(h1));
        lo2[i * 2 + 1] = __floats2bfloat162_rn(v.z - __bfloat162float(h2),
                                               v.w - __bfloat162float(h3));
    }
}

// ---------------- routing ----------------
__global__ void zero_counts_kernel() {
    if (threadIdx.x < EE) { g_cnt[threadIdx.x] = 0; g_cur[threadIdx.x] = 0; }
}

__global__ void gate_kernel(const float* __restrict__ x, const float* __restrict__ gw) {
    int t = blockIdx.x, tid = threadIdx.x;
    float acc[EE];
#pragma unroll
    for (int e = 0; e < EE; e++) acc[e] = 0.f;
    for (int h = tid; h < HH; h += 256) {
        float xv = x[(size_t)t * HH + h];
#pragma unroll
        for (int e = 0; e < EE; e++) acc[e] += xv * gw[e * HH + h];
    }
    __shared__ float red[EE][256];
#pragma unroll
    for (int e = 0; e < EE; e++) red[e][tid] = acc[e];
    __syncthreads();
    for (int s = 128; s > 0; s >>= 1) {
        if (tid < s) {
#pragma unroll
            for (int e = 0; e < EE; e++) red[e][tid] += red[e][tid + s];
        }
        __syncthreads();
    }
    if (tid == 0) {
        float lg[EE];
#pragma unroll
        for (int e = 0; e < EE; e++) lg[e] = red[e][0];
        int i1 = 0;
#pragma unroll
        for (int e = 1; e < EE; e++) if (lg[e] > lg[i1]) i1 = e;
        int i2 = -1;
#pragma unroll
        for (int e = 0; e < EE; e++)
            if (e != i1 && (i2 < 0 || lg[e] > lg[i2])) i2 = e;
        float w1 = 1.f / (1.f + expf(lg[i2] - lg[i1]));
        g_topk_idx[t * 2 + 0] = i1; g_topk_idx[t * 2 + 1] = i2;
        g_topk_w[t * 2 + 0] = w1;   g_topk_w[t * 2 + 1] = 1.f - w1;
        atomicAdd(&g_cnt[i1], 1);   atomicAdd(&g_cnt[i2], 1);
    }
}

__global__ void scan_kernel() {
    if (threadIdx.x == 0) {
        int s = 0;
        for (int e = 0; e < EE; e++) { g_off[e] = s; s += g_cnt[e]; }
    }
}

__global__ void scatter_kernel() {
    int t = blockIdx.x * blockDim.x + threadIdx.x;
    if (t >= TT) return;
#pragma unroll
    for (int k = 0; k < 2; k++) {
        int e = g_topk_idx[t * 2 + k];
        int pos = g_off[e] + atomicAdd(&g_cur[e], 1);
        g_rowtok[pos] = t;
        g_roww[pos]   = g_topk_w[t * 2 + k];
    }
}

// ---------------- split-bf16 HMMA GEMM with cp.async pipeline ----------------
// IS_FC1=1: D = gather(xhi/xlo) @ w1^T, epilogue bias+SwiGLU -> g_acthi/lo
// IS_FC1=0: D = g_act @ w2^T,           epilogue bias + weighted atomic combine -> out
template <int IS_FC1>
__global__ void __launch_bounds__(256) moe_gemm(
    const float* __restrict__ bias, float* __restrict__ outp)
{
    extern __shared__ char dsm[];
    __shared__ int s_row[BM];

    int e   = blockIdx.z;
    int cnt = g_cnt[e];
    int m0  = blockIdx.y * BM;
    if (m0 >= cnt) return;
    int off = g_off[e];
    int n0  = blockIdx.x * BN;
    const int NTOT = IS_FC1 ? I2 : HH;
    int tid = threadIdx.x;

    const __nv_bfloat16* Ahi = IS_FC1 ? g_xhi : g_acthi;
    const __nv_bfloat16* Alo = IS_FC1 ? g_xlo : g_actlo;
    const __nv_bfloat16* Bhi = (IS_FC1 ? g_w1hi : g_w2hi) + (size_t)e * NTOT * KDIM;
    const __nv_bfloat16* Blo = (IS_FC1 ? g_w1lo : g_w2lo) + (size_t)e * NTOT * KDIM;

    if (tid < BM) {
        int m = m0 + tid;
        if (IS_FC1) s_row[tid] = (m < cnt) ? g_rowtok[off + m] : g_rowtok[off];
        else        s_row[tid] = off + ((m < cnt) ? m : cnt - 1);
    }
    __syncthreads();

    uint32_t smb = s2u(dsm);

    // cp.async assignments: idx in {tid, tid+256}; r = idx>>2 (row), cs = idx&3 (16B seg)
    size_t aoff[2], boff[2];
    uint32_t dstoff[2];
#pragma unroll
    for (int i = 0; i < 2; i++) {
        int idx = tid + i * 256;
        int r = idx >> 2, cs = idx & 3;
        aoff[i] = (size_t)s_row[r] * KDIM + cs * 8;
        boff[i] = (size_t)(n0 + r) * KDIM + cs * 8;
        dstoff[i] = r * (STRD * 2) + cs * 16;
    }

    // prologue: issue chunks 0..2
#pragma unroll
    for (int c = 0; c < NSTAGE - 1; c++) {
        uint32_t sb = smb + c * STG;
#pragma unroll
        for (int i = 0; i < 2; i++) {
            cpasync16(sb + dstoff[i],             Ahi + aoff[i] + c * BK);
            cpasync16(sb + dstoff[i] + TILEB,     Alo + aoff[i] + c * BK);
            cpasync16(sb + dstoff[i] + 2 * TILEB, Bhi + boff[i] + c * BK);
            cpasync16(sb + dstoff[i] + 3 * TILEB, Blo + boff[i] + c * BK);
        }
        cp_commit();
    }

    int lane = tid & 31, wid = tid >> 5;
    int wm = (wid & 3) * 32;
    int wn = (wid >> 2) * 64;
    int lrow = lane & 15;
    int lcol8 = (lane >> 4) * 8;

    float acc[2][8][4];
#pragma unroll
    for (int i = 0; i < 2; i++)
#pragma unroll
        for (int j = 0; j < 8; j++)
#pragma unroll
            for (int k = 0; k < 4; k++) acc[i][j][k] = 0.f;

    for (int c = 0; c < NCHUNK; c++) {
        cp_wait<NSTAGE - 2>();
        __syncthreads();
        uint32_t sb = smb + (c & (NSTAGE - 1)) * STG;
#pragma unroll
        for (int ks = 0; ks < 2; ks++) {
            uint32_t ah[2][4], al[2][4];
#pragma unroll
            for (int mi = 0; mi < 2; mi++) {
                uint32_t ad = sb + (wm + mi * 16 + lrow) * (STRD * 2) + (ks * 16 + lcol8) * 2;
                ldm_x4(ah[mi], ad);
                ldm_x4(al[mi], ad + TILEB);
            }
#pragma unroll
            for (int bq = 0; bq < 4; bq++) {
                uint32_t bh[4], bl[4];
                uint32_t bd = sb + 2 * TILEB + (wn + bq * 16 + lrow) * (STRD * 2) + (ks * 16 + lcol8) * 2;
                ldm_x4(bh, bd);
                ldm_x4(bl, bd + TILEB);
#pragma unroll
                for (int mi = 0; mi < 2; mi++) {
                    mma16816(acc[mi][bq * 2 + 0], ah[mi], bh[0], bh[2]);
                    mma16816(acc[mi][bq * 2 + 0], ah[mi], bl[0], bl[2]);
                    mma16816(acc[mi][bq * 2 + 0], al[mi], bh[0], bh[2]);
                    mma16816(acc[mi][bq * 2 + 1], ah[mi], bh[1], bh[3]);
                    mma16816(acc[mi][bq * 2 + 1], ah[mi], bl[1], bl[3]);
                    mma16816(acc[mi][bq * 2 + 1], al[mi], bh[1], bh[3]);
                }
            }
        }
        // prefetch chunk c + NSTAGE-1
        int cn = c + NSTAGE - 1;
        if (cn < NCHUNK) {
            uint32_t sb2 = smb + (cn & (NSTAGE - 1)) * STG;
#pragma unroll
            for (int i = 0; i < 2; i++) {
                cpasync16(sb2 + dstoff[i],             Ahi + aoff[i] + cn * BK);
                cpasync16(sb2 + dstoff[i] + TILEB,     Alo + aoff[i] + cn * BK);
                cpasync16(sb2 + dstoff[i] + 2 * TILEB, Bhi + boff[i] + cn * BK);
                cpasync16(sb2 + dstoff[i] + 3 * TILEB, Blo + boff[i] + cn * BK);
            }
        }
        cp_commit();
    }

    // -------- epilogue --------
#pragma unroll
    for (int mi = 0; mi < 2; mi++) {
#pragma unroll
        for (int h = 0; h < 2; h++) {
            int m = m0 + wm + mi * 16 + (lane >> 2) + h * 8;
            if (m >= cnt) continue;
            if (IS_FC1) {
                size_t rowo = (size_t)(off + m) * II;
#pragma unroll
                for (int nb = 0; nb < 8; nb++) {
                    int f = n0 + wn + nb * 8 + (lane & 3) * 2;    // even column
                    float g = acc[mi][nb][h * 2 + 0] + bias[(size_t)e * NTOT + f];
                    float l = acc[mi][nb][h * 2 + 1] + bias[(size_t)e * NTOT + f + 1];
                    float sg = 1.f / (1.f + expf(-1.702f * g));
                    float a  = g * sg * (l + 1.f);
                    __nv_bfloat16 hb = __float2bfloat16_rn(a);
                    g_acthi[rowo + (f >> 1)] = hb;
                    g_actlo[rowo + (f >> 1)] = __float2bfloat16_rn(a - __bfloat162float(hb));
                }
            } else {
                int row = off + m;
                int tok = g_rowtok[row];
                float w = g_roww[row];
                size_t o = (size_t)tok * HH;
#pragma unroll
                for (int nb = 0; nb < 8; nb++) {
                    int f = n0 + wn + nb * 8 + (lane & 3) * 2;
                    float y0 = acc[mi][nb][h * 2 + 0] + bias[(size_t)e * NTOT + f];
                    float y1 = acc[mi][nb][h * 2 + 1] + bias[(size_t)e * NTOT + f + 1];
                    atomicAdd(&outp[o + f],     w * y0);
                    atomicAdd(&outp[o + f + 1], w * y1);
                }
            }
        }
    }
}

// ---------------- launch ----------------
extern "C" void kernel_launch(void* const* d_in, const int* in_sizes, int n_in,
                              void* d_out, int out_size) {
    const float* x  = (const float*)d_in[0];
    const float* gw = (const float*)d_in[1];
    const float* w1 = (const float*)d_in[2];
    const float* b1 = (const float*)d_in[3];
    const float* w2 = (const float*)d_in[4];
    const float* b2 = (const float*)d_in[5];
    float* out = (float*)d_out;

    static int smem_set = 0;
    if (!smem_set) {
        cudaFuncSetAttribute(moe_gemm<1>, cudaFuncAttributeMaxDynamicSharedMemorySize, SMEM_DYN);
        cudaFuncSetAttribute(moe_gemm<0>, cudaFuncAttributeMaxDynamicSharedMemorySize, SMEM_DYN);
        smem_set = 1;
    }

    __nv_bfloat162 *xhi, *xlo, *w1hi, *w1lo, *w2hi, *w2lo;
    cudaGetSymbolAddress((void**)&xhi,  g_xhi);
    cudaGetSymbolAddress((void**)&xlo,  g_xlo);
    cudaGetSymbolAddress((void**)&w1hi, g_w1hi);
    cudaGetSymbolAddress((void**)&w1lo, g_w1lo);
    cudaGetSymbolAddress((void**)&w2hi, g_w2hi);
    cudaGetSymbolAddress((void**)&w2lo, g_w2lo);

    cudaMemsetAsync(out, 0, (size_t)TT * HH * sizeof(float), 0);
    convert_split<<<2048, 256>>>((const float4*)x,  xhi,  xlo,  (size_t)TT * HH / 4);
    convert_split<<<4096, 256>>>((const float4*)w1, w1hi, w1lo, (size_t)EE * I2 * HH / 4);
    convert_split<<<4096, 256>>>((const float4*)w2, w2hi, w2lo, (size_t)EE * HH * II / 4);
    zero_counts_kernel<<<1, 32>>>();
    gate_kernel<<<TT, 256>>>(x, gw);
    scan_kernel<<<1, 32>>>();
    scatter_kernel<<<(TT + 255) / 256, 256>>>();
    moe_gemm<1><<<dim3(I2 / BN, NASS / BM, EE), 256, SMEM_DYN>>>(b1, nullptr);
    moe_gemm<0><<<dim3(HH / BN, NASS / BM, EE), 256, SMEM_DYN>>>(b2, out);
}

// round 7
// speedup vs baseline: 1.9789x; 1.9789x over previous
#include <cuda_runtime.h>
#include <cuda_bf16.h>
#include <cstdint>
#include <math.h>

// Problem constants (B=4, S=1024, H=2048, I=2048, E=8, top_k=2)
#define TT   4096
#define HH   2048
#define EE   8
#define II   2048
#define I2   4096
#define NASS (TT * 2)
#define KDIM 2048
#define BM   128
#define BN   128
#define BK   32
#define NCHUNK (KDIM / BK)   // 64
#define STRD 40              // halves per smem row (80B; conflict-free ldmatrix)
#define TILEB (BM * STRD * 2)          // 10240 B per tile
#define STG   (4 * TILEB)              // 40960 B per stage? NO -> see below
#undef STG
#define STG   (4 * 8192)               // 32768 B per stage (Ah, Al, Bh, Bl @ 8KB each)
#undef TILEB
#define TILEB 8192                     // 128 rows x 32 cols bf16 packed with STRD rows? see layout
#define NSTAGE 3
// NOTE: tiles stored with STRD=40 halves/row -> 128*40*2 = 10240B each; recompute:
#undef TILEB
#undef STG
#define TILEB (BM * STRD * 2)          // 10240 B
#define STG   (4 * TILEB)              // 40960 B? -> too big for 2 CTAs at 3 stages
// Use STRD=32 (no pad) but XOR-swizzle columns to avoid bank conflicts instead of padding.
#undef STRD
#undef TILEB
#undef STG
#define STRD 32
#define TILEB (BM * STRD * 2)          // 8192 B
#define STG   (4 * TILEB)              // 32768 B
#define SMEM_DYN (NSTAGE * STG)        // 98304 B -> 2 CTAs/SM

// Swizzle: 16B segment cs (0..3) within row r -> cs ^ (r & 3). ldmatrix rows r..r+7
// then hit segments {cs^(r&3)} which for 8 consecutive rows covers each bank group
// twice in distinct 16B columns -> conflict-free; cp.async writes use same map.
#define SWZ(r, cs) ((cs) ^ ((r) & 3))

// ---------------- scratch (device globals) ----------------
__device__ int   g_topk_idx[TT * 2];
__device__ float g_topk_w[TT * 2];
__device__ int   g_cnt[EE];
__device__ int   g_off[EE];
__device__ int   g_cur[EE];
__device__ int   g_rowtok[NASS];
__device__ float g_roww[NASS];
__device__ __nv_bfloat16 g_xhi[(size_t)TT * HH],  g_xlo[(size_t)TT * HH];
__device__ __nv_bfloat16 g_w1hi[(size_t)EE * I2 * HH], g_w1lo[(size_t)EE * I2 * HH];
__device__ __nv_bfloat16 g_w2hi[(size_t)EE * HH * II], g_w2lo[(size_t)EE * HH * II];
__device__ __nv_bfloat16 g_acthi[(size_t)NASS * II], g_actlo[(size_t)NASS * II];

// ---------------- helpers ----------------
__device__ __forceinline__ uint32_t s2u(const void* p) {
    uint32_t a;
    asm("{ .reg .u64 t; cvta.to.shared.u64 t, %1; cvt.u32.u64 %0, t; }" : "=r"(a) : "l"(p));
    return a;
}
__device__ __forceinline__ void cpasync16(uint32_t dst, const void* src) {
    asm volatile("cp.async.cg.shared.global [%0], [%1], 16;" :: "r"(dst), "l"(src));
}
__device__ __forceinline__ void cp_commit() { asm volatile("cp.async.commit_group;"); }
template <int N>
__device__ __forceinline__ void cp_wait() { asm volatile("cp.async.wait_group %0;" :: "n"(N)); }

__device__ __forceinline__ void ldm_x4(uint32_t* r, uint32_t addr) {
    asm volatile("ldmatrix.sync.aligned.m8n8.x4.shared.b16 {%0,%1,%2,%3}, [%4];"
                 : "=r"(r[0]), "=r"(r[1]), "=r"(r[2]), "=r"(r[3]) : "r"(addr));
}
__device__ __forceinline__ void mma16816(float* d, const uint32_t* a, uint32_t b0, uint32_t b1) {
    asm volatile("mma.sync.aligned.m16n8k16.row.col.f32.bf16.bf16.f32 "
                 "{%0,%1,%2,%3}, {%4,%5,%6,%7}, {%8,%9}, {%0,%1,%2,%3};"
                 : "+f"(d[0]), "+f"(d[1]), "+f"(d[2]), "+f"(d[3])
                 : "r"(a[0]), "r"(a[1]), "r"(a[2]), "r"(a[3]), "r"(b0), "r"(b1));
}

// ldmatrix fragment fetch with swizzled 16B columns.
// Fragment at (rowbase, ks) needs rows rowbase..rowbase+15, 16B cols [ks*2, ks*2+1].
// Per-lane address: row = rowbase + (lane&15), cs16 = ks*2 + (lane>>4)  (x4 form)
__device__ __forceinline__ uint32_t frag_addr(uint32_t tilebase, int rowbase, int ks, int lane) {
    int row  = rowbase + (lane & 15);
    int cs16 = ks * 2 + (lane >> 4);
    return tilebase + row * (STRD * 2) + SWZ(row, cs16) * 16;
}

// ---------------- split-convert ----------------
__global__ void convert_split(const float4* __restrict__ src,
                              __nv_bfloat162* __restrict__ hi2,
                              __nv_bfloat162* __restrict__ lo2, size_t n4) {
    size_t stride = (size_t)gridDim.x * blockDim.x;
    for (size_t i = (size_t)blockIdx.x * blockDim.x + threadIdx.x; i < n4; i += stride) {
        float4 v = src[i];
        __nv_bfloat16 h0 = __float2bfloat16_rn(v.x), h1 = __float2bfloat16_rn(v.y);
        __nv_bfloat16 h2 = __float2bfloat16_rn(v.z), h3 = __float2bfloat16_rn(v.w);
        hi2[i * 2 + 0] = __halves2bfloat162(h0, h1);
        hi2[i * 2 + 1] = __halves2bfloat162(h2, h3);
        lo2[i * 2 + 0] = __floats2bfloat162_rn(v.x - __bfloat162float(h0),
                                               v.y - __bfloat162float(h1));
        lo2[i * 2 + 1] = __floats2bfloat162_rn(v.z - __bfloat162float(h2),
                                               v.w - __bfloat162float(h3));
    }
}

// ---------------- routing ----------------
__global__ void zero_counts_kernel() {
    if (threadIdx.x < EE) { g_cnt[threadIdx.x] = 0; g_cur[threadIdx.x] = 0; }
}

__global__ void gate_kernel(const float* __restrict__ x, const float* __restrict__ gw) {
    int t = blockIdx.x, tid = threadIdx.x;
    float acc[EE];
#pragma unroll
    for (int e = 0; e < EE; e++) acc[e] = 0.f;
    for (int h = tid; h < HH; h += 256) {
        float xv = x[(size_t)t * HH + h];
#pragma unroll
        for (int e = 0; e < EE; e++) acc[e] += xv * gw[e * HH + h];
    }
    __shared__ float red[EE][256];
#pragma unroll
    for (int e = 0; e < EE; e++) red[e][tid] = acc[e];
    __syncthreads();
    for (int s = 128; s > 0; s >>= 1) {
        if (tid < s) {
#pragma unroll
            for (int e = 0; e < EE; e++) red[e][tid] += red[e][tid + s];
        }
        __syncthreads();
    }
    if (tid == 0) {
        float lg[EE];
#pragma unroll
        for (int e = 0; e < EE; e++) lg[e] = red[e][0];
        int i1 = 0;
#pragma unroll
        for (int e = 1; e < EE; e++) if (lg[e] > lg[i1]) i1 = e;
        int i2 = -1;
#pragma unroll
        for (int e = 0; e < EE; e++)
            if (e != i1 && (i2 < 0 || lg[e] > lg[i2])) i2 = e;
        float w1 = 1.f / (1.f + expf(lg[i2] - lg[i1]));
        g_topk_idx[t * 2 + 0] = i1; g_topk_idx[t * 2 + 1] = i2;
        g_topk_w[t * 2 + 0] = w1;   g_topk_w[t * 2 + 1] = 1.f - w1;
        atomicAdd(&g_cnt[i1], 1);   atomicAdd(&g_cnt[i2], 1);
    }
}

__global__ void scan_kernel() {
    if (threadIdx.x == 0) {
        int s = 0;
        for (int e = 0; e < EE; e++) { g_off[e] = s; s += g_cnt[e]; }
    }
}

__global__ void scatter_kernel() {
    int t = blockIdx.x * blockDim.x + threadIdx.x;
    if (t >= TT) return;
#pragma unroll
    for (int k = 0; k < 2; k++) {
        int e = g_topk_idx[t * 2 + k];
        int pos = g_off[e] + atomicAdd(&g_cur[e], 1);
        g_rowtok[pos] = t;
        g_roww[pos]   = g_topk_w[t * 2 + k];
    }
}

// ---------------- split-bf16 HMMA GEMM, cp.async 3-stage, 2 CTAs/SM ----------------
template <int IS_FC1>
__global__ void __launch_bounds__(256, 2) moe_gemm(
    const float* __restrict__ bias, float* __restrict__ outp)
{
    extern __shared__ char dsm[];
    __shared__ int s_row[BM];

    int e   = blockIdx.z;
    int cnt = g_cnt[e];
    int m0  = blockIdx.y * BM;
    if (m0 >= cnt) return;
    int off = g_off[e];
    int n0  = blockIdx.x * BN;
    const int NTOT = IS_FC1 ? I2 : HH;
    int tid = threadIdx.x;

    const __nv_bfloat16* Ahi = IS_FC1 ? g_xhi : g_acthi;
    const __nv_bfloat16* Alo = IS_FC1 ? g_xlo : g_actlo;
    const __nv_bfloat16* Bhi = (IS_FC1 ? g_w1hi : g_w2hi) + (size_t)e * NTOT * KDIM;
    const __nv_bfloat16* Blo = (IS_FC1 ? g_w1lo : g_w2lo) + (size_t)e * NTOT * KDIM;

    if (tid < BM) {
        int m = m0 + tid;
        if (IS_FC1) s_row[tid] = (m < cnt) ? g_rowtok[off + m] : g_rowtok[off];
        else        s_row[tid] = off + ((m < cnt) ? m : cnt - 1);
    }
    __syncthreads();

    uint32_t smb = s2u(dsm);

    // cp.async: idx in {tid, tid+256}; r = idx>>2, cs = idx&3 (16B segment)
    size_t aoff[2], boff[2];
    uint32_t dstoff[2];
#pragma unroll
    for (int i = 0; i < 2; i++) {
        int idx = tid + i * 256;
        int r = idx >> 2, cs = idx & 3;
        aoff[i] = (size_t)s_row[r] * KDIM + cs * 8;
        boff[i] = (size_t)(n0 + r) * KDIM + cs * 8;
        dstoff[i] = r * (STRD * 2) + SWZ(r, cs) * 16;
    }

#pragma unroll
    for (int c = 0; c < NSTAGE - 1; c++) {
        uint32_t sb = smb + c * STG;
#pragma unroll
        for (int i = 0; i < 2; i++) {
            cpasync16(sb + dstoff[i],             Ahi + aoff[i] + c * BK);
            cpasync16(sb + dstoff[i] + TILEB,     Alo + aoff[i] + c * BK);
            cpasync16(sb + dstoff[i] + 2 * TILEB, Bhi + boff[i] + c * BK);
            cpasync16(sb + dstoff[i] + 3 * TILEB, Blo + boff[i] + c * BK);
        }
        cp_commit();
    }

    int lane = tid & 31, wid = tid >> 5;
    int wm = (wid & 3) * 32;
    int wn = (wid >> 2) * 64;

    float acc[2][8][4];
#pragma unroll
    for (int i = 0; i < 2; i++)
#pragma unroll
        for (int j = 0; j < 8; j++)
#pragma unroll
            for (int k = 0; k < 4; k++) acc[i][j][k] = 0.f;

    int stage = 0;
    for (int c = 0; c < NCHUNK; c++) {
        cp_wait<NSTAGE - 2>();
        __syncthreads();
        uint32_t sb = smb + stage * STG;
#pragma unroll
        for (int ks = 0; ks < 2; ks++) {
            uint32_t ah[2][4], al[2][4];
#pragma unroll
            for (int mi = 0; mi < 2; mi++) {
                ldm_x4(ah[mi], frag_addr(sb,             wm + mi * 16, ks, lane));
                ldm_x4(al[mi], frag_addr(sb + TILEB,     wm + mi * 16, ks, lane));
            }
#pragma unroll
            for (int bq = 0; bq < 4; bq++) {
                uint32_t bh[4], bl[4];
                ldm_x4(bh, frag_addr(sb + 2 * TILEB, wn + bq * 16, ks, lane));
                ldm_x4(bl, frag_addr(sb + 3 * TILEB, wn + bq * 16, ks, lane));
#pragma unroll
                for (int mi = 0; mi < 2; mi++) {
                    mma16816(acc[mi][bq * 2 + 0], ah[mi], bh[0], bh[2]);
                    mma16816(acc[mi][bq * 2 + 0], ah[mi], bl[0], bl[2]);
                    mma16816(acc[mi][bq * 2 + 0], al[mi], bh[0], bh[2]);
                    mma16816(acc[mi][bq * 2 + 1], ah[mi], bh[1], bh[3]);
                    mma16816(acc[mi][bq * 2 + 1], ah[mi], bl[1], bl[3]);
                    mma16816(acc[mi][bq * 2 + 1], al[mi], bh[1], bh[3]);
                }
            }
        }
        int cn = c + NSTAGE - 1;
        if (cn < NCHUNK) {
            int st2 = stage;  // (c + NSTAGE-1) % NSTAGE == c % NSTAGE when NSTAGE... no:
            // stage of cn = (cn) % NSTAGE; compute incrementally below
            st2 = cn % NSTAGE;
            uint32_t sb2 = smb + st2 * STG;
#pragma unroll
            for (int i = 0; i < 2; i++) {
                cpasync16(sb2 + dstoff[i],             Ahi + aoff[i] + cn * BK);
                cpasync16(sb2 + dstoff[i] + TILEB,     Alo + aoff[i] + cn * BK);
                cpasync16(sb2 + dstoff[i] + 2 * TILEB, Bhi + boff[i] + cn * BK);
                cpasync16(sb2 + dstoff[i] + 3 * TILEB, Blo + boff[i] + cn * BK);
            }
        }
        cp_commit();
        stage = (stage + 1 == NSTAGE) ? 0 : stage + 1;
    }

    // -------- epilogue --------
#pragma unroll
    for (int mi = 0; mi < 2; mi++) {
#pragma unroll
        for (int h = 0; h < 2; h++) {
            int m = m0 + wm + mi * 16 + (lane >> 2) + h * 8;
            if (m >= cnt) continue;
            if (IS_FC1) {
                size_t rowo = (size_t)(off + m) * II;
#pragma unroll
                for (int nb = 0; nb < 8; nb++) {
                    int f = n0 + wn + nb * 8 + (lane & 3) * 2;
                    float g = acc[mi][nb][h * 2 + 0] + bias[(size_t)e * NTOT + f];
                    float l = acc[mi][nb][h * 2 + 1] + bias[(size_t)e * NTOT + f + 1];
                    float sg = 1.f / (1.f + expf(-1.702f * g));
                    float a  = g * sg * (l + 1.f);
                    __nv_bfloat16 hb = __float2bfloat16_rn(a);
                    g_acthi[rowo + (f >> 1)] = hb;
                    g_actlo[rowo + (f >> 1)] = __float2bfloat16_rn(a - __bfloat162float(hb));
                }
            } else {
                int row = off + m;
                int tok = g_rowtok[row];
                float w = g_roww[row];
                size_t o = (size_t)tok * HH;
#pragma unroll
                for (int nb = 0; nb < 8; nb++) {
                    int f = n0 + wn + nb * 8 + (lane & 3) * 2;
                    float y0 = acc[mi][nb][h * 2 + 0] + bias[(size_t)e * NTOT + f];
                    float y1 = acc[mi][nb][h * 2 + 1] + bias[(size_t)e * NTOT + f + 1];
                    atomicAdd(&outp[o + f],     w * y0);
                    atomicAdd(&outp[o + f + 1], w * y1);
                }
            }
        }
    }
}

// ---------------- launch ----------------
extern "C" void kernel_launch(void* const* d_in, const int* in_sizes, int n_in,
                              void* d_out, int out_size) {
    const float* x  = (const float*)d_in[0];
    const float* gw = (const float*)d_in[1];
    const float* w1 = (const float*)d_in[2];
    const float* b1 = (const float*)d_in[3];
    const float* w2 = (const float*)d_in[4];
    const float* b2 = (const float*)d_in[5];
    float* out = (float*)d_out;

    cudaFuncSetAttribute(moe_gemm<1>, cudaFuncAttributeMaxDynamicSharedMemorySize, SMEM_DYN);
    cudaFuncSetAttribute(moe_gemm<0>, cudaFuncAttributeMaxDynamicSharedMemorySize, SMEM_DYN);

    __nv_bfloat162 *xhi, *xlo, *w1hi, *w1lo, *w2hi, *w2lo;
    cudaGetSymbolAddress((void**)&xhi,  g_xhi);
    cudaGetSymbolAddress((void**)&xlo,  g_xlo);
    cudaGetSymbolAddress((void**)&w1hi, g_w1hi);
    cudaGetSymbolAddress((void**)&w1lo, g_w1lo);
    cudaGetSymbolAddress((void**)&w2hi, g_w2hi);
    cudaGetSymbolAddress((void**)&w2lo, g_w2lo);

    cudaMemsetAsync(out, 0, (size_t)TT * HH * sizeof(float), 0);
    convert_split<<<2048, 256>>>((const float4*)x,  xhi,  xlo,  (size_t)TT * HH / 4);
    convert_split<<<4096, 256>>>((const float4*)w1, w1hi, w1lo, (size_t)EE * I2 * HH / 4);
    convert_split<<<4096, 256>>>((const float4*)w2, w2hi, w2lo, (size_t)EE * HH * II / 4);
    zero_counts_kernel<<<1, 32>>>();
    gate_kernel<<<TT, 256>>>(x, gw);
    scan_kernel<<<1, 32>>>();
    scatter_kernel<<<(TT + 255) / 256, 256>>>();
    moe_gemm<1><<<dim3(I2 / BN, NASS / BM, EE), 256, SMEM_DYN>>>(b1, nullptr);
    moe_gemm<0><<<dim3(HH / BN, NASS / BM, EE), 256, SMEM_DYN>>>(b2, out);
}